// round 14
// baseline (speedup 1.0000x reference)
#include <cuda_runtime.h>
#include <cuda_bf16.h>
#include <mma.h>
#include <math.h>
#include <stdint.h>

using namespace nvcuda;

// ---------------- problem constants ----------------
#define B_     32
#define S_     197
#define BS_    (B_ * S_)      // 6304
#define D_     768
#define F_     3072
#define H_     12
#define DH_    64
#define L_     12
#define NPATCH 196
#define NCLS_  1000
#define QS_    2304           // fused qkv row stride

typedef __nv_bfloat16 bf16;

// ---------------- scratch ----------------
__device__ float g_x   [BS_ * D_];
__device__ float g_lnb [BS_ * D_];
__device__ bf16  g_lnh [BS_ * D_];
__device__ bf16  g_lnl [BS_ * D_];
__device__ float g_qkv [(size_t)BS_ * QS_];
__device__ bf16  g_attnh[BS_ * D_];
__device__ bf16  g_attnl[BS_ * D_];
__device__ bf16  g_ffhh[(size_t)BS_ * F_];
__device__ bf16  g_ffhl[(size_t)BS_ * F_];
__device__ float g_sc  [(size_t)B_ * H_ * S_ * S_];
__device__ bf16  g_imh [B_ * NPATCH * D_];
__device__ bf16  g_iml [B_ * NPATCH * D_];
__device__ float g_pe  [B_ * NPATCH * D_];
// pre-split weights (bf16 hi/lo), [K,N] layout
__device__ bf16  g_wpt_h[D_ * D_];
__device__ bf16  g_wpt_l[D_ * D_];
__device__ bf16  g_wqkv_h[(size_t)L_ * D_ * QS_];
__device__ bf16  g_wqkv_l[(size_t)L_ * D_ * QS_];
__device__ float g_bqkv [L_ * QS_];
__device__ bf16  g_wo_h[(size_t)L_ * D_ * D_];
__device__ bf16  g_wo_l[(size_t)L_ * D_ * D_];
__device__ bf16  g_wf1_h[(size_t)L_ * D_ * F_];
__device__ bf16  g_wf1_l[(size_t)L_ * D_ * F_];
__device__ bf16  g_wf2_h[(size_t)L_ * F_ * D_];
__device__ bf16  g_wf2_l[(size_t)L_ * F_ * D_];

// ---------------- helpers ----------------
__device__ __forceinline__ void splitv(float v, bf16& h, bf16& l) {
    h = __float2bfloat16(v);
    l = __float2bfloat16(v - __bfloat162float(h));
}
__device__ __forceinline__ uint32_t smem_u32(const void* p) {
    return (uint32_t)__cvta_generic_to_shared(p);
}
__device__ __forceinline__ void cp16(uint32_t dst, const void* src, bool pred) {
    int sz = pred ? 16 : 0;
    asm volatile("cp.async.cg.shared.global [%0], [%1], 16, %2;\n"
                 :: "r"(dst), "l"(src), "r"(sz));
}

// ---------------- prep: weight splitting (vectorized x4) ----------------
__global__ void split_kernel(const float* __restrict__ src, bf16* __restrict__ h,
                             bf16* __restrict__ l, size_t n) {
    size_t i = ((size_t)blockIdx.x * 256 + threadIdx.x) * 4;
    if (i >= n) return;
    float4 v = *reinterpret_cast<const float4*>(src + i);
    bf16 h0,l0,h1,l1,h2,l2,h3,l3;
    splitv(v.x,h0,l0); splitv(v.y,h1,l1); splitv(v.z,h2,l2); splitv(v.w,h3,l3);
    *reinterpret_cast<__nv_bfloat162*>(h + i)     = __halves2bfloat162(h0, h1);
    *reinterpret_cast<__nv_bfloat162*>(h + i + 2) = __halves2bfloat162(h2, h3);
    *reinterpret_cast<__nv_bfloat162*>(l + i)     = __halves2bfloat162(l0, l1);
    *reinterpret_cast<__nv_bfloat162*>(l + i + 2) = __halves2bfloat162(l2, l3);
}

__global__ void qkv_split_kernel(const float* __restrict__ Wq, const float* __restrict__ Wk,
                                 const float* __restrict__ Wv,
                                 bf16* __restrict__ h, bf16* __restrict__ l) {
    size_t i = ((size_t)blockIdx.x * 256 + threadIdx.x) * 4;
    if (i >= (size_t)L_ * D_ * QS_) return;
    int n = (int)(i % QS_);
    size_t rest = i / QS_;
    int k = (int)(rest % D_);
    int lay = (int)(rest / D_);
    const float* src = (n < 768) ? Wq : (n < 1536) ? Wk : Wv;
    float4 v = *reinterpret_cast<const float4*>(src + ((size_t)lay * D_ + k) * D_ + (n % 768));
    bf16 h0,l0,h1,l1,h2,l2,h3,l3;
    splitv(v.x,h0,l0); splitv(v.y,h1,l1); splitv(v.z,h2,l2); splitv(v.w,h3,l3);
    *reinterpret_cast<__nv_bfloat162*>(h + i)     = __halves2bfloat162(h0, h1);
    *reinterpret_cast<__nv_bfloat162*>(h + i + 2) = __halves2bfloat162(h2, h3);
    *reinterpret_cast<__nv_bfloat162*>(l + i)     = __halves2bfloat162(l0, l1);
    *reinterpret_cast<__nv_bfloat162*>(l + i + 2) = __halves2bfloat162(l2, l3);
}

__global__ void qkv_bias_kernel(const float* __restrict__ bq, const float* __restrict__ bk,
                                const float* __restrict__ bv, float* __restrict__ out) {
    int i = blockIdx.x * 256 + threadIdx.x;
    if (i >= L_ * QS_) return;
    int n = i % QS_, lay = i / QS_;
    const float* src = (n < 768) ? bq : (n < 1536) ? bk : bv;
    out[i] = src[lay * D_ + (n % 768)];
}

__global__ void transpose_split_kernel(const float* __restrict__ W,
                                       bf16* __restrict__ h, bf16* __restrict__ l) {
    int idx = blockIdx.x * 256 + threadIdx.x;
    if (idx >= D_ * D_) return;
    int d = idx / D_, k = idx % D_;
    splitv(W[idx], h[k * D_ + d], l[k * D_ + d]);
}

// ---------------- im2col (writes bf16 hi/lo) ----------------
__global__ void im2col_kernel(const float* __restrict__ X,
                              bf16* __restrict__ oh, bf16* __restrict__ ol) {
    int idx = blockIdx.x * blockDim.x + threadIdx.x;
    if (idx >= B_ * NPATCH * D_) return;
    int col = idx % D_;
    int row = idx / D_;
    int b  = row / NPATCH;
    int pp = row % NPATCH;
    int ph = pp / 14, pw = pp % 14;
    int c = col >> 8;
    int p = (col >> 4) & 15;
    int q = col & 15;
    float v = X[((size_t)(b * 3 + c) * 224 + (ph * 16 + p)) * 224 + (pw * 16 + q)];
    splitv(v, oh[idx], ol[idx]);
}

__global__ void assemble_kernel(const float* __restrict__ pe, const float* __restrict__ cls,
                                const float* __restrict__ pos, float* __restrict__ x) {
    int idx = blockIdx.x * blockDim.x + threadIdx.x;
    if (idx >= BS_ * D_) return;
    int d  = idx % D_;
    int bs = idx / D_;
    int s = bs % S_;
    int b = bs / S_;
    float v = (s == 0) ? cls[d] : pe[((size_t)b * NPATCH + (s - 1)) * D_ + d];
    x[idx] = v + pos[s * D_ + d];
}

// ---------------- dual-bf16 tensor-core GEMM ----------------
// 256 threads, 8 warps in 2x4 grid, warp tile 64x64 (4x4 fp32 acc frags).
// BM=128 BN=256 BK=32, cp.async double buffer, 1 sync/iter.
// epi: 0 -> Cf = v ; 1 -> Cf = v + R ; 2 -> (Ch,Cl) = split(GELU(v))
#define PA 40
#define PB 264
#define GEMM_SMEM 118784

__global__ __launch_bounds__(256, 1)
void gemm_dual_kernel(const bf16* __restrict__ Agh, const bf16* __restrict__ Agl,
                      const bf16* __restrict__ Bgh, const bf16* __restrict__ Bgl,
                      const float* __restrict__ bias, const float* __restrict__ R,
                      float* __restrict__ Cf, bf16* __restrict__ Ch, bf16* __restrict__ Cl,
                      int M, int N, int K, int epi)
{
    extern __shared__ char dsm[];
    bf16* sAh = (bf16*)dsm;                       // 2 * 128*PA
    bf16* sAl = sAh + 2 * 128 * PA;
    bf16* sBh = sAl + 2 * 128 * PA;               // 2 * 32*PB
    bf16* sBl = sBh + 2 * 32 * PB;
    float* sStage = (float*)(sBl + 2 * 32 * PB);  // 8 * 16*20

    const int tid  = threadIdx.x;
    const int wid  = tid >> 5;
    const int lane = tid & 31;
    const int warpRow = wid >> 2;     // 0..1 (64 rows)
    const int warpCol = wid & 3;      // 0..3 (64 cols)
    const int brow = blockIdx.y * 128;
    const int bcol = blockIdx.x * 256;

    // A loader: 512 chunks of 16B (128 rows x 4); thread does c=tid, c=tid+256
    const int aRow0 = tid >> 2;            // 0..63
    const int aC0   = (tid & 3) * 8;
    const bool aOk0 = (brow + aRow0) < M;
    const bool aOk1 = (brow + aRow0 + 64) < M;
    const int aRowG0 = aOk0 ? (brow + aRow0) : (M - 1);
    const int aRowG1 = aOk1 ? (brow + aRow0 + 64) : (M - 1);
    const bf16* aSrcH0 = Agh + (size_t)aRowG0 * K + aC0;
    const bf16* aSrcL0 = Agl + (size_t)aRowG0 * K + aC0;
    const bf16* aSrcH1 = Agh + (size_t)aRowG1 * K + aC0;
    const bf16* aSrcL1 = Agl + (size_t)aRowG1 * K + aC0;
    const uint32_t aDstH0 = smem_u32(sAh + aRow0 * PA + aC0);
    const uint32_t aDstH1 = smem_u32(sAh + (aRow0 + 64) * PA + aC0);
    const uint32_t aDstL0 = smem_u32(sAl + aRow0 * PA + aC0);
    const uint32_t aDstL1 = smem_u32(sAl + (aRow0 + 64) * PA + aC0);
    // B loader: 1024 chunks (32 rows x 32); thread does q=0..3: c=tid+q*256
    const int bR0 = tid >> 5;              // base row 0..7, +8 per q
    const int bC8 = (tid & 31) * 8;
    uint32_t bDstH[4], bDstL[4];
#pragma unroll
    for (int q = 0; q < 4; q++) {
        bDstH[q] = smem_u32(sBh + (bR0 + q * 8) * PB + bC8);
        bDstL[q] = smem_u32(sBl + (bR0 + q * 8) * PB + bC8);
    }

    const int bufA = 128 * PA * 2;
    const int bufB = 32 * PB * 2;

    auto issue = [&](int k0, int buf) {
        cp16(aDstH0 + buf * bufA, aSrcH0 + k0, aOk0);
        cp16(aDstH1 + buf * bufA, aSrcH1 + k0, aOk1);
        cp16(aDstL0 + buf * bufA, aSrcL0 + k0, aOk0);
        cp16(aDstL1 + buf * bufA, aSrcL1 + k0, aOk1);
        const bf16* bh = Bgh + (size_t)k0 * N + bcol + bC8;
        const bf16* bl = Bgl + (size_t)k0 * N + bcol + bC8;
#pragma unroll
        for (int q = 0; q < 4; q++) {
            cp16(bDstH[q] + buf * bufB, bh + (size_t)(bR0 + q * 8) * N, true);
            cp16(bDstL[q] + buf * bufB, bl + (size_t)(bR0 + q * 8) * N, true);
        }
    };

    wmma::fragment<wmma::accumulator, 16, 16, 16, float> acc[4][4];
#pragma unroll
    for (int i = 0; i < 4; i++)
#pragma unroll
        for (int j = 0; j < 4; j++) wmma::fill_fragment(acc[i][j], 0.0f);

    const int T = K / 32;
    issue(0, 0);
    asm volatile("cp.async.commit_group;\n");
    asm volatile("cp.async.wait_group 0;\n");
    __syncthreads();

    for (int it = 0; it < T; ++it) {
        if (it + 1 < T) {
            issue((it + 1) * 32, (it + 1) & 1);
            asm volatile("cp.async.commit_group;\n");
        }

        const int buf = it & 1;
        const bf16* cAh = sAh + buf * 128 * PA;
        const bf16* cAl = sAl + buf * 128 * PA;
        const bf16* cBh = sBh + buf * 32 * PB;
        const bf16* cBl = sBl + buf * 32 * PB;

#pragma unroll
        for (int kk = 0; kk < 32; kk += 16) {
            wmma::fragment<wmma::matrix_b, 16, 16, 16, bf16, wmma::row_major> fbh[4], fbl[4];
#pragma unroll
            for (int j = 0; j < 4; j++) {
                wmma::load_matrix_sync(fbh[j], cBh + kk * PB + warpCol * 64 + j * 16, PB);
                wmma::load_matrix_sync(fbl[j], cBl + kk * PB + warpCol * 64 + j * 16, PB);
            }
#pragma unroll
            for (int i = 0; i < 4; i++) {
                wmma::fragment<wmma::matrix_a, 16, 16, 16, bf16, wmma::row_major> fah, fal;
                int r = warpRow * 64 + i * 16;
                wmma::load_matrix_sync(fah, cAh + r * PA + kk, PA);
                wmma::load_matrix_sync(fal, cAl + r * PA + kk, PA);
#pragma unroll
                for (int j = 0; j < 4; j++) {
                    wmma::mma_sync(acc[i][j], fah, fbh[j], acc[i][j]);
                    wmma::mma_sync(acc[i][j], fah, fbl[j], acc[i][j]);
                    wmma::mma_sync(acc[i][j], fal, fbh[j], acc[i][j]);
                }
            }
        }

        if (it + 1 < T) asm volatile("cp.async.wait_group 0;\n");
        __syncthreads();
    }

    // ---- epilogue ----
    float* st = sStage + wid * 16 * 20;
#pragma unroll
    for (int i = 0; i < 4; i++) {
#pragma unroll
        for (int j = 0; j < 4; j++) {
            wmma::store_matrix_sync(st, acc[i][j], 20, wmma::mem_row_major);
            __syncwarp();
            int gr0 = brow + warpRow * 64 + i * 16;
            int gc0 = bcol + warpCol * 64 + j * 16;
#pragma unroll
            for (int e = 0; e < 8; e++) {
                int idx = e * 32 + lane;
                int r = idx >> 4, c = idx & 15;
                int gr = gr0 + r;
                if (gr < M) {
                    size_t off = (size_t)gr * N + gc0 + c;
                    float v = st[r * 20 + c] + bias[gc0 + c];
                    if (epi == 1) {
                        Cf[off] = v + R[off];
                    } else if (epi == 2) {
                        v = 0.5f * v * (1.0f + erff(v * 0.70710678118654752f));
                        bf16 hh, ll; splitv(v, hh, ll);
                        Ch[off] = hh; Cl[off] = ll;
                    } else {
                        Cf[off] = v;
                    }
                }
            }
            __syncwarp();
        }
    }
}

// ---------------- LayerNorm ----------------
__global__ void layernorm_kernel(const float* __restrict__ x, const float* __restrict__ g,
                                 const float* __restrict__ b, float* __restrict__ out,
                                 bf16* __restrict__ oh, bf16* __restrict__ ol)
{
    __shared__ float xs[D_];
    __shared__ float red[8];
    __shared__ float s_mean, s_rstd;

    int row = blockIdx.x;
    const float* xr = x + (size_t)row * D_;
    int tid  = threadIdx.x;
    int lane = tid & 31, warp = tid >> 5;

    float s = 0.f;
    for (int i = tid; i < D_; i += 256) { float v = xr[i]; xs[i] = v; s += v; }
#pragma unroll
    for (int o = 16; o; o >>= 1) s += __shfl_xor_sync(0xffffffffu, s, o);
    if (lane == 0) red[warp] = s;
    __syncthreads();
    if (tid == 0) {
        float t = 0.f;
#pragma unroll
        for (int w = 0; w < 8; w++) t += red[w];
        s_mean = t * (1.0f / D_);
    }
    __syncthreads();
    float m = s_mean;

    float v2 = 0.f;
    for (int i = tid; i < D_; i += 256) { float dv = xs[i] - m; v2 += dv * dv; }
#pragma unroll
    for (int o = 16; o; o >>= 1) v2 += __shfl_xor_sync(0xffffffffu, v2, o);
    if (lane == 0) red[warp] = v2;
    __syncthreads();
    if (tid == 0) {
        float t = 0.f;
#pragma unroll
        for (int w = 0; w < 8; w++) t += red[w];
        s_rstd = rsqrtf(t * (1.0f / D_) + 1e-5f);
    }
    __syncthreads();
    float rstd = s_rstd;

    size_t base = (size_t)row * D_;
    for (int i = tid; i < D_; i += 256) {
        float v = (xs[i] - m) * rstd * g[i] + b[i];
        out[base + i] = v;
        bf16 hh, ll; splitv(v, hh, ll);
        oh[base + i] = hh; ol[base + i] = ll;
    }
}

// ---------------- fused QK^T + softmax (fp32, scores stay in smem) ----------------
#define SCP 260
#define QKS_SMEM ((64 * 68 * 2 + 64 * SCP) * 4)

__global__ __launch_bounds__(256)
void qk_softmax_kernel(const float* __restrict__ QKV, float* __restrict__ P)
{
    extern __shared__ float sm[];
    float* Qs = sm;                 // [d][r] pitch 68
    float* Ks = Qs + 64 * 68;       // [d][t] pitch 68
    float* sc = Ks + 64 * 68;       // [r][t] pitch SCP

    const int bh = blockIdx.y;
    const int b = bh / H_, h = bh % H_;
    const int s0 = blockIdx.x * 64;
    const int tid = threadIdx.x;
    const int tx = tid & 15, ty = tid >> 4;

    const float* Qb = QKV + (size_t)b * S_ * QS_ + h * DH_;
    const float* Kb = Qb + 768;

#pragma unroll
    for (int k = 0; k < 16; k++) {
        int idx = tid + k * 256;
        int r = idx >> 6, d = idx & 63;
        float qv = 0.f;
        if (s0 + r < S_) qv = Qb[(size_t)(s0 + r) * QS_ + d];
        Qs[d * 68 + r] = qv;
    }

    for (int tt = 0; tt < 4; tt++) {
        __syncthreads();
#pragma unroll
        for (int k = 0; k < 16; k++) {
            int idx = tid + k * 256;
            int r = idx >> 6, d = idx & 63;
            float kv = 0.f;
            int t = tt * 64 + r;
            if (t < S_) kv = Kb[(size_t)t * QS_ + d];
            Ks[d * 68 + r] = kv;
        }
        __syncthreads();

        float acc[4][4];
#pragma unroll
        for (int i = 0; i < 4; i++)
#pragma unroll
            for (int j = 0; j < 4; j++) acc[i][j] = 0.f;

#pragma unroll 4
        for (int d = 0; d < 64; d++) {
            float4 a  = *reinterpret_cast<const float4*>(&Qs[d * 68 + ty * 4]);
            float4 bb = *reinterpret_cast<const float4*>(&Ks[d * 68 + tx * 4]);
            float ar[4] = {a.x, a.y, a.z, a.w};
            float br[4] = {bb.x, bb.y, bb.z, bb.w};
#pragma unroll
            for (int i = 0; i < 4; i++)
#pragma unroll
                for (int j = 0; j < 4; j++) acc[i][j] += ar[i] * br[j];
        }

#pragma unroll
        for (int i = 0; i < 4; i++)
#pragma unroll
            for (int j = 0; j < 4; j++)
                sc[(ty * 4 + i) * SCP + tt * 64 + tx * 4 + j] = acc[i][j] * 0.125f;
    }
    __syncthreads();

    const int wid = tid >> 5, lane = tid & 31;
    float* Pb = P + (size_t)bh * S_ * S_;
    for (int r = wid * 8; r < wid * 8 + 8; r++) {
        int s = s0 + r;
        if (s >= S_) continue;
        float* row = sc + r * SCP;
        float m = -1e30f;
        for (int t = lane; t < S_; t += 32) m = fmaxf(m, row[t]);
#pragma unroll
        for (int o = 16; o; o >>= 1) m = fmaxf(m, __shfl_xor_sync(0xffffffffu, m, o));
        float ssum = 0.f;
        for (int t = lane; t < S_; t += 32) { float e = expf(row[t] - m); row[t] = e; ssum += e; }
#pragma unroll
        for (int o = 16; o; o >>= 1) ssum += __shfl_xor_sync(0xffffffffu, ssum, o);
        float inv = 1.0f / ssum;
        float* orow = Pb + (size_t)s * S_;
        for (int t = lane; t < S_; t += 32) orow[t] = row[t] * inv;
    }
}

// ---------------- attention: O = P @ V (fp32, writes bf16 hi/lo) ----------------
__global__ __launch_bounds__(256)
void pv_kernel(const float* __restrict__ P, const float* __restrict__ QKV,
               bf16* __restrict__ Oh, bf16* __restrict__ Ol)
{
    const int PITCH = 68;
    __shared__ __align__(16) float Ps[32 * PITCH];
    __shared__ __align__(16) float Vs[32 * PITCH];

    int bh = blockIdx.y;
    int b = bh / H_, h = bh % H_;
    int s0 = blockIdx.x * 64;
    const float* Pb = P + (size_t)bh * S_ * S_;
    const float* Vb = QKV + (size_t)b * S_ * QS_ + 1536 + h * DH_;
    int tid = threadIdx.x;
    int tx = tid & 15, ty = tid >> 4;

    float acc[4][4];
#pragma unroll
    for (int i = 0; i < 4; i++)
#pragma unroll
        for (int j = 0; j < 4; j++) acc[i][j] = 0.f;

    for (int t0 = 0; t0 < S_; t0 += 32) {
#pragma unroll
        for (int k = 0; k < 8; k++) {
            int idx = tid + k * 256;
            int r = idx >> 5, t = idx & 31;
            float pv = 0.f;
            if (s0 + r < S_ && t0 + t < S_) pv = Pb[(size_t)(s0 + r) * S_ + t0 + t];
            Ps[t * PITCH + r] = pv;
        }
#pragma unroll
        for (int k = 0; k < 8; k++) {
            int idx = tid + k * 256;
            int t = idx >> 6, d = idx & 63;
            float vv = 0.f;
            if (t0 + t < S_) vv = Vb[(size_t)(t0 + t) * QS_ + d];
            Vs[t * PITCH + d] = vv;
        }
        __syncthreads();

#pragma unroll 4
        for (int t = 0; t < 32; t++) {
            float4 a = *reinterpret_cast<const float4*>(&Ps[t * PITCH + ty * 4]);
            float4 bb = *reinterpret_cast<const float4*>(&Vs[t * PITCH + tx * 4]);
            float ar[4] = {a.x, a.y, a.z, a.w};
            float br[4] = {bb.x, bb.y, bb.z, bb.w};
#pragma unroll
            for (int i = 0; i < 4; i++)
#pragma unroll
                for (int j = 0; j < 4; j++) acc[i][j] += ar[i] * br[j];
        }
        __syncthreads();
    }

#pragma unroll
    for (int i = 0; i < 4; i++) {
        int s = s0 + ty * 4 + i;
        if (s >= S_) continue;
#pragma unroll
        for (int j = 0; j < 4; j++) {
            int d = tx * 4 + j;
            size_t off = ((size_t)(b * S_ + s)) * D_ + h * DH_ + d;
            bf16 hh, ll; splitv(acc[i][j], hh, ll);
            Oh[off] = hh; Ol[off] = ll;
        }
    }
}

// ---------------- classification head ----------------
__global__ void head_kernel(const float* __restrict__ Xn, const float* __restrict__ W,
                            const float* __restrict__ bias, float* __restrict__ out)
{
    __shared__ float xs[D_];
    int b = blockIdx.y;
    const float* xr = Xn + (size_t)b * S_ * D_;
    for (int i = threadIdx.x; i < D_; i += 256) xs[i] = xr[i];
    __syncthreads();

    int n = blockIdx.x * 256 + threadIdx.x;
    if (n >= NCLS_) return;
    float s = bias[n];
    for (int k = 0; k < D_; k++) s += xs[k] * W[(size_t)k * NCLS_ + n];
    out[b * NCLS_ + n] = s;
}

// ---------------- host launch ----------------
static inline void run_gemm(const bf16* Ah, const bf16* Al, const bf16* Bh, const bf16* Bl,
                            const float* bias, const float* R,
                            float* Cf, bf16* Ch, bf16* Cl, int M, int N, int K, int epi)
{
    dim3 grid(N / 256, (M + 127) / 128);
    gemm_dual_kernel<<<grid, 256, GEMM_SMEM>>>(Ah, Al, Bh, Bl, bias, R, Cf, Ch, Cl, M, N, K, epi);
}

extern "C" void kernel_launch(void* const* d_in, const int* in_sizes, int n_in,
                              void* d_out, int out_size)
{
    const float* X       = (const float*)d_in[0];
    const float* patch_w = (const float*)d_in[1];
    const float* patch_b = (const float*)d_in[2];
    const float* cls_tok = (const float*)d_in[3];
    const float* pos_emb = (const float*)d_in[4];
    const float* ln1_g   = (const float*)d_in[5];
    const float* ln1_b   = (const float*)d_in[6];
    const float* Wq      = (const float*)d_in[7];
    const float* bq      = (const float*)d_in[8];
    const float* Wk      = (const float*)d_in[9];
    const float* bk      = (const float*)d_in[10];
    const float* Wv      = (const float*)d_in[11];
    const float* bv      = (const float*)d_in[12];
    const float* Wo      = (const float*)d_in[13];
    const float* bo      = (const float*)d_in[14];
    const float* ln2_g   = (const float*)d_in[15];
    const float* ln2_b   = (const float*)d_in[16];
    const float* Wf1     = (const float*)d_in[17];
    const float* bf1     = (const float*)d_in[18];
    const float* Wf2     = (const float*)d_in[19];
    const float* bf2     = (const float*)d_in[20];
    const float* lnf_g   = (const float*)d_in[21];
    const float* lnf_b   = (const float*)d_in[22];
    const float* head_w  = (const float*)d_in[23];
    const float* head_b  = (const float*)d_in[24];
    float* out = (float*)d_out;
    (void)in_sizes; (void)n_in; (void)out_size;

    cudaFuncSetAttribute(gemm_dual_kernel, cudaFuncAttributeMaxDynamicSharedMemorySize, GEMM_SMEM);
    cudaFuncSetAttribute(qk_softmax_kernel, cudaFuncAttributeMaxDynamicSharedMemorySize, QKS_SMEM);

    float *px, *plnf, *pqkv, *ppe, *psc, *pbqkv;
    bf16 *plnh, *plnl, *pattnh, *pattnl, *pffhh, *pffhl, *pimh, *piml;
    bf16 *pwpth, *pwptl, *pwqkvh, *pwqkvl, *pwoh, *pwol, *pwf1h, *pwf1l, *pwf2h, *pwf2l;
    cudaGetSymbolAddress((void**)&px,    g_x);
    cudaGetSymbolAddress((void**)&plnf,  g_lnb);
    cudaGetSymbolAddress((void**)&plnh,  g_lnh);
    cudaGetSymbolAddress((void**)&plnl,  g_lnl);
    cudaGetSymbolAddress((void**)&pqkv,  g_qkv);
    cudaGetSymbolAddress((void**)&pattnh,g_attnh);
    cudaGetSymbolAddress((void**)&pattnl,g_attnl);
    cudaGetSymbolAddress((void**)&pffhh, g_ffhh);
    cudaGetSymbolAddress((void**)&pffhl, g_ffhl);
    cudaGetSymbolAddress((void**)&psc,   g_sc);
    cudaGetSymbolAddress((void**)&pimh,  g_imh);
    cudaGetSymbolAddress((void**)&piml,  g_iml);
    cudaGetSymbolAddress((void**)&ppe,   g_pe);
    cudaGetSymbolAddress((void**)&pwpth, g_wpt_h);
    cudaGetSymbolAddress((void**)&pwptl, g_wpt_l);
    cudaGetSymbolAddress((void**)&pwqkvh,g_wqkv_h);
    cudaGetSymbolAddress((void**)&pwqkvl,g_wqkv_l);
    cudaGetSymbolAddress((void**)&pbqkv, g_bqkv);
    cudaGetSymbolAddress((void**)&pwoh,  g_wo_h);
    cudaGetSymbolAddress((void**)&pwol,  g_wo_l);
    cudaGetSymbolAddress((void**)&pwf1h, g_wf1_h);
    cudaGetSymbolAddress((void**)&pwf1l, g_wf1_l);
    cudaGetSymbolAddress((void**)&pwf2h, g_wf2_h);
    cudaGetSymbolAddress((void**)&pwf2l, g_wf2_l);

    // --- prep: split weights (vectorized) ---
    {
        size_t nqkv = (size_t)L_ * D_ * QS_;
        qkv_split_kernel<<<(unsigned)((nqkv / 4 + 255) / 256), 256>>>(Wq, Wk, Wv, pwqkvh, pwqkvl);
        qkv_bias_kernel<<<(L_ * QS_ + 255) / 256, 256>>>(bq, bk, bv, pbqkv);
        size_t nwo = (size_t)L_ * D_ * D_;
        split_kernel<<<(unsigned)((nwo / 4 + 255) / 256), 256>>>(Wo, pwoh, pwol, nwo);
        size_t nf = (size_t)L_ * D_ * F_;
        split_kernel<<<(unsigned)((nf / 4 + 255) / 256), 256>>>(Wf1, pwf1h, pwf1l, nf);
        split_kernel<<<(unsigned)((nf / 4 + 255) / 256), 256>>>(Wf2, pwf2h, pwf2l, nf);
        transpose_split_kernel<<<(D_ * D_ + 255) / 256, 256>>>(patch_w, pwpth, pwptl);
    }

    // --- patch embedding ---
    {
        int n1 = B_ * NPATCH * D_;
        im2col_kernel<<<(n1 + 255) / 256, 256>>>(X, pimh, piml);
        run_gemm(pimh, piml, pwpth, pwptl, patch_b, nullptr,
                 ppe, nullptr, nullptr, B_ * NPATCH, D_, D_, 0);
        int n2 = BS_ * D_;
        assemble_kernel<<<(n2 + 255) / 256, 256>>>(ppe, cls_tok, pos_emb, px);
    }

    for (int l = 0; l < L_; l++) {
        layernorm_kernel<<<BS_, 256>>>(px, ln1_g + l * D_, ln1_b + l * D_, plnf, plnh, plnl);

        // fused QKV GEMM -> fp32 qkv
        run_gemm(plnh, plnl, pwqkvh + (size_t)l * D_ * QS_, pwqkvl + (size_t)l * D_ * QS_,
                 pbqkv + l * QS_, nullptr, pqkv, nullptr, nullptr, BS_, QS_, D_, 0);

        // fused QK^T + softmax, then PV
        {
            dim3 grid((S_ + 63) / 64, B_ * H_);
            qk_softmax_kernel<<<grid, 256, QKS_SMEM>>>(pqkv, psc);
            pv_kernel<<<grid, 256>>>(psc, pqkv, pattnh, pattnl);
        }

        // out proj + residual
        run_gemm(pattnh, pattnl, pwoh + (size_t)l * D_ * D_, pwol + (size_t)l * D_ * D_,
                 bo + l * D_, px, px, nullptr, nullptr, BS_, D_, D_, 1);

        layernorm_kernel<<<BS_, 256>>>(px, ln2_g + l * D_, ln2_b + l * D_, plnf, plnh, plnl);

        // FFN1 (GELU) + FFN2 (+residual)
        run_gemm(plnh, plnl, pwf1h + (size_t)l * D_ * F_, pwf1l + (size_t)l * D_ * F_,
                 bf1 + l * F_, nullptr, nullptr, pffhh, pffhl, BS_, F_, D_, 2);
        run_gemm(pffhh, pffhl, pwf2h + (size_t)l * F_ * D_, pwf2l + (size_t)l * F_ * D_,
                 bf2 + l * D_, px, px, nullptr, nullptr, BS_, D_, F_, 1);
    }

    layernorm_kernel<<<BS_, 256>>>(px, lnf_g, lnf_b, plnf, plnh, plnl);
    {
        dim3 grid((NCLS_ + 255) / 256, B_);
        head_kernel<<<grid, 256>>>(plnf, head_w, head_b, out);
    }
}

// round 15
// speedup vs baseline: 1.0186x; 1.0186x over previous
#include <cuda_runtime.h>
#include <cuda_bf16.h>
#include <mma.h>
#include <math.h>
#include <stdint.h>

using namespace nvcuda;

// ---------------- problem constants ----------------
#define B_     32
#define S_     197
#define BS_    (B_ * S_)      // 6304
#define D_     768
#define F_     3072
#define H_     12
#define DH_    64
#define L_     12
#define NPATCH 196
#define NCLS_  1000
#define QS_    2304           // fused qkv row stride

typedef __nv_bfloat16 bf16;

// ---------------- scratch ----------------
__device__ float g_x   [BS_ * D_];
__device__ float g_lnb [BS_ * D_];
__device__ bf16  g_lnh [BS_ * D_];
__device__ bf16  g_lnl [BS_ * D_];
__device__ float g_qkv [(size_t)BS_ * QS_];
__device__ bf16  g_attnh[BS_ * D_];
__device__ bf16  g_attnl[BS_ * D_];
__device__ bf16  g_ffhh[(size_t)BS_ * F_];
__device__ bf16  g_ffhl[(size_t)BS_ * F_];
__device__ float g_sc  [(size_t)B_ * H_ * S_ * S_];
__device__ bf16  g_imh [B_ * NPATCH * D_];
__device__ bf16  g_iml [B_ * NPATCH * D_];
__device__ float g_pe  [B_ * NPATCH * D_];
// pre-split weights (bf16 hi/lo), [K,N] layout
__device__ bf16  g_wpt_h[D_ * D_];
__device__ bf16  g_wpt_l[D_ * D_];
__device__ bf16  g_wqkv_h[(size_t)L_ * D_ * QS_];
__device__ bf16  g_wqkv_l[(size_t)L_ * D_ * QS_];
__device__ float g_bqkv [L_ * QS_];
__device__ bf16  g_wo_h[(size_t)L_ * D_ * D_];
__device__ bf16  g_wo_l[(size_t)L_ * D_ * D_];
__device__ bf16  g_wf1_h[(size_t)L_ * D_ * F_];
__device__ bf16  g_wf1_l[(size_t)L_ * D_ * F_];
__device__ bf16  g_wf2_h[(size_t)L_ * F_ * D_];
__device__ bf16  g_wf2_l[(size_t)L_ * F_ * D_];

// ---------------- helpers ----------------
__device__ __forceinline__ void splitv(float v, bf16& h, bf16& l) {
    h = __float2bfloat16(v);
    l = __float2bfloat16(v - __bfloat162float(h));
}
__device__ __forceinline__ uint32_t smem_u32(const void* p) {
    return (uint32_t)__cvta_generic_to_shared(p);
}
__device__ __forceinline__ void cp16(uint32_t dst, const void* src, bool pred) {
    int sz = pred ? 16 : 0;
    asm volatile("cp.async.cg.shared.global [%0], [%1], 16, %2;\n"
                 :: "r"(dst), "l"(src), "r"(sz));
}

// ---------------- prep: weight splitting (vectorized x4) ----------------
__global__ void split_kernel(const float* __restrict__ src, bf16* __restrict__ h,
                             bf16* __restrict__ l, size_t n) {
    size_t i = ((size_t)blockIdx.x * 256 + threadIdx.x) * 4;
    if (i >= n) return;
    float4 v = *reinterpret_cast<const float4*>(src + i);
    bf16 h0,l0,h1,l1,h2,l2,h3,l3;
    splitv(v.x,h0,l0); splitv(v.y,h1,l1); splitv(v.z,h2,l2); splitv(v.w,h3,l3);
    *reinterpret_cast<__nv_bfloat162*>(h + i)     = __halves2bfloat162(h0, h1);
    *reinterpret_cast<__nv_bfloat162*>(h + i + 2) = __halves2bfloat162(h2, h3);
    *reinterpret_cast<__nv_bfloat162*>(l + i)     = __halves2bfloat162(l0, l1);
    *reinterpret_cast<__nv_bfloat162*>(l + i + 2) = __halves2bfloat162(l2, l3);
}

__global__ void qkv_split_kernel(const float* __restrict__ Wq, const float* __restrict__ Wk,
                                 const float* __restrict__ Wv,
                                 bf16* __restrict__ h, bf16* __restrict__ l) {
    size_t i = ((size_t)blockIdx.x * 256 + threadIdx.x) * 4;
    if (i >= (size_t)L_ * D_ * QS_) return;
    int n = (int)(i % QS_);
    size_t rest = i / QS_;
    int k = (int)(rest % D_);
    int lay = (int)(rest / D_);
    const float* src = (n < 768) ? Wq : (n < 1536) ? Wk : Wv;
    float4 v = *reinterpret_cast<const float4*>(src + ((size_t)lay * D_ + k) * D_ + (n % 768));
    bf16 h0,l0,h1,l1,h2,l2,h3,l3;
    splitv(v.x,h0,l0); splitv(v.y,h1,l1); splitv(v.z,h2,l2); splitv(v.w,h3,l3);
    *reinterpret_cast<__nv_bfloat162*>(h + i)     = __halves2bfloat162(h0, h1);
    *reinterpret_cast<__nv_bfloat162*>(h + i + 2) = __halves2bfloat162(h2, h3);
    *reinterpret_cast<__nv_bfloat162*>(l + i)     = __halves2bfloat162(l0, l1);
    *reinterpret_cast<__nv_bfloat162*>(l + i + 2) = __halves2bfloat162(l2, l3);
}

__global__ void qkv_bias_kernel(const float* __restrict__ bq, const float* __restrict__ bk,
                                const float* __restrict__ bv, float* __restrict__ out) {
    int i = blockIdx.x * 256 + threadIdx.x;
    if (i >= L_ * QS_) return;
    int n = i % QS_, lay = i / QS_;
    const float* src = (n < 768) ? bq : (n < 1536) ? bk : bv;
    out[i] = src[lay * D_ + (n % 768)];
}

__global__ void transpose_split_kernel(const float* __restrict__ W,
                                       bf16* __restrict__ h, bf16* __restrict__ l) {
    int idx = blockIdx.x * 256 + threadIdx.x;
    if (idx >= D_ * D_) return;
    int d = idx / D_, k = idx % D_;
    splitv(W[idx], h[k * D_ + d], l[k * D_ + d]);
}

// ---------------- im2col (writes bf16 hi/lo) ----------------
__global__ void im2col_kernel(const float* __restrict__ X,
                              bf16* __restrict__ oh, bf16* __restrict__ ol) {
    int idx = blockIdx.x * blockDim.x + threadIdx.x;
    if (idx >= B_ * NPATCH * D_) return;
    int col = idx % D_;
    int row = idx / D_;
    int b  = row / NPATCH;
    int pp = row % NPATCH;
    int ph = pp / 14, pw = pp % 14;
    int c = col >> 8;
    int p = (col >> 4) & 15;
    int q = col & 15;
    float v = X[((size_t)(b * 3 + c) * 224 + (ph * 16 + p)) * 224 + (pw * 16 + q)];
    splitv(v, oh[idx], ol[idx]);
}

__global__ void assemble_kernel(const float* __restrict__ pe, const float* __restrict__ cls,
                                const float* __restrict__ pos, float* __restrict__ x) {
    int idx = blockIdx.x * blockDim.x + threadIdx.x;
    if (idx >= BS_ * D_) return;
    int d  = idx % D_;
    int bs = idx / D_;
    int s = bs % S_;
    int b = bs / S_;
    float v = (s == 0) ? cls[d] : pe[((size_t)b * NPATCH + (s - 1)) * D_ + d];
    x[idx] = v + pos[s * D_ + d];
}

// ---------------- dual-bf16 tensor-core GEMM ----------------
// 256 threads, 8 warps in 4x2 grid, warp tile 32x64 (2x4 fp32 acc frags).
// BM=128 BN=128 BK=32, cp.async double buffer, 1 sync/iter, 2 CTAs/SM.
// epi: 0 -> Cf = v ; 1 -> Cf = v + R ; 2 -> (Ch,Cl) = split(GELU(v))
#define PA 40
#define PB 136
#define GEMM_SMEM 86016

__global__ __launch_bounds__(256, 2)
void gemm_dual_kernel(const bf16* __restrict__ Agh, const bf16* __restrict__ Agl,
                      const bf16* __restrict__ Bgh, const bf16* __restrict__ Bgl,
                      const float* __restrict__ bias, const float* __restrict__ R,
                      float* __restrict__ Cf, bf16* __restrict__ Ch, bf16* __restrict__ Cl,
                      int M, int N, int K, int epi)
{
    extern __shared__ char dsm[];
    bf16* sAh = (bf16*)dsm;                       // 2 * 128*PA
    bf16* sAl = sAh + 2 * 128 * PA;
    bf16* sBh = sAl + 2 * 128 * PA;               // 2 * 32*PB
    bf16* sBl = sBh + 2 * 32 * PB;
    float* sStage = (float*)(sBl + 2 * 32 * PB);  // 8 * 16*20

    const int tid  = threadIdx.x;
    const int wid  = tid >> 5;
    const int lane = tid & 31;
    const int warpRow = wid & 3;      // 0..3 (32 rows each)
    const int warpCol = wid >> 2;     // 0..1 (64 cols each)
    const int brow = blockIdx.y * 128;
    const int bcol = blockIdx.x * 128;

    // A tile 128x32 = 512 16B-chunks; B tile 32x128 = 512 chunks; 2 each/thread
    int aR[2], aC[2], bR[2], bC[2];
    bool aOk[2];
    const bf16* aSH[2]; const bf16* aSL[2];
    uint32_t aDH[2], aDL[2], bDH[2], bDL[2];
#pragma unroll
    for (int q = 0; q < 2; q++) {
        int c = tid + q * 256;
        aR[q] = c >> 2;  aC[q] = (c & 3) * 8;
        aOk[q] = (brow + aR[q]) < M;
        int arg = aOk[q] ? (brow + aR[q]) : (M - 1);
        aSH[q] = Agh + (size_t)arg * K + aC[q];
        aSL[q] = Agl + (size_t)arg * K + aC[q];
        aDH[q] = smem_u32(sAh + aR[q] * PA + aC[q]);
        aDL[q] = smem_u32(sAl + aR[q] * PA + aC[q]);
        bR[q] = c >> 4;  bC[q] = (c & 15) * 8;
        bDH[q] = smem_u32(sBh + bR[q] * PB + bC[q]);
        bDL[q] = smem_u32(sBl + bR[q] * PB + bC[q]);
    }

    const int bufA = 128 * PA * 2;    // bytes per A buffer
    const int bufB = 32 * PB * 2;     // bytes per B buffer

    auto issue = [&](int k0, int buf) {
#pragma unroll
        for (int q = 0; q < 2; q++) {
            cp16(aDH[q] + buf * bufA, aSH[q] + k0, aOk[q]);
            cp16(aDL[q] + buf * bufA, aSL[q] + k0, aOk[q]);
            const bf16* bh = Bgh + (size_t)(k0 + bR[q]) * N + bcol + bC[q];
            const bf16* bl = Bgl + (size_t)(k0 + bR[q]) * N + bcol + bC[q];
            cp16(bDH[q] + buf * bufB, bh, true);
            cp16(bDL[q] + buf * bufB, bl, true);
        }
    };

    wmma::fragment<wmma::accumulator, 16, 16, 16, float> acc[2][4];
#pragma unroll
    for (int i = 0; i < 2; i++)
#pragma unroll
        for (int j = 0; j < 4; j++) wmma::fill_fragment(acc[i][j], 0.0f);

    const int T = K / 32;
    issue(0, 0);
    asm volatile("cp.async.commit_group;\n");
    asm volatile("cp.async.wait_group 0;\n");
    __syncthreads();

    for (int it = 0; it < T; ++it) {
        if (it + 1 < T) {
            issue((it + 1) * 32, (it + 1) & 1);
            asm volatile("cp.async.commit_group;\n");
        }

        const int buf = it & 1;
        const bf16* cAh = sAh + buf * 128 * PA;
        const bf16* cAl = sAl + buf * 128 * PA;
        const bf16* cBh = sBh + buf * 32 * PB;
        const bf16* cBl = sBl + buf * 32 * PB;

#pragma unroll
        for (int kk = 0; kk < 32; kk += 16) {
            wmma::fragment<wmma::matrix_b, 16, 16, 16, bf16, wmma::row_major> fbh[4], fbl[4];
#pragma unroll
            for (int j = 0; j < 4; j++) {
                wmma::load_matrix_sync(fbh[j], cBh + kk * PB + warpCol * 64 + j * 16, PB);
                wmma::load_matrix_sync(fbl[j], cBl + kk * PB + warpCol * 64 + j * 16, PB);
            }
#pragma unroll
            for (int i = 0; i < 2; i++) {
                wmma::fragment<wmma::matrix_a, 16, 16, 16, bf16, wmma::row_major> fah, fal;
                int r = warpRow * 32 + i * 16;
                wmma::load_matrix_sync(fah, cAh + r * PA + kk, PA);
                wmma::load_matrix_sync(fal, cAl + r * PA + kk, PA);
#pragma unroll
                for (int j = 0; j < 4; j++) {
                    wmma::mma_sync(acc[i][j], fah, fbh[j], acc[i][j]);
                    wmma::mma_sync(acc[i][j], fah, fbl[j], acc[i][j]);
                    wmma::mma_sync(acc[i][j], fal, fbh[j], acc[i][j]);
                }
            }
        }

        if (it + 1 < T) asm volatile("cp.async.wait_group 0;\n");
        __syncthreads();
    }

    // ---- epilogue ----
    float* st = sStage + wid * 16 * 20;
#pragma unroll
    for (int i = 0; i < 2; i++) {
#pragma unroll
        for (int j = 0; j < 4; j++) {
            wmma::store_matrix_sync(st, acc[i][j], 20, wmma::mem_row_major);
            __syncwarp();
            int gr0 = brow + warpRow * 32 + i * 16;
            int gc0 = bcol + warpCol * 64 + j * 16;
#pragma unroll
            for (int e = 0; e < 8; e++) {
                int idx = e * 32 + lane;
                int r = idx >> 4, c = idx & 15;
                int gr = gr0 + r;
                if (gr < M) {
                    size_t off = (size_t)gr * N + gc0 + c;
                    float v = st[r * 20 + c] + bias[gc0 + c];
                    if (epi == 1) {
                        Cf[off] = v + R[off];
                    } else if (epi == 2) {
                        v = 0.5f * v * (1.0f + erff(v * 0.70710678118654752f));
                        bf16 hh, ll; splitv(v, hh, ll);
                        Ch[off] = hh; Cl[off] = ll;
                    } else {
                        Cf[off] = v;
                    }
                }
            }
            __syncwarp();
        }
    }
}

// ---------------- LayerNorm ----------------
__global__ void layernorm_kernel(const float* __restrict__ x, const float* __restrict__ g,
                                 const float* __restrict__ b, float* __restrict__ out,
                                 bf16* __restrict__ oh, bf16* __restrict__ ol)
{
    __shared__ float xs[D_];
    __shared__ float red[8];
    __shared__ float s_mean, s_rstd;

    int row = blockIdx.x;
    const float* xr = x + (size_t)row * D_;
    int tid  = threadIdx.x;
    int lane = tid & 31, warp = tid >> 5;

    float s = 0.f;
    for (int i = tid; i < D_; i += 256) { float v = xr[i]; xs[i] = v; s += v; }
#pragma unroll
    for (int o = 16; o; o >>= 1) s += __shfl_xor_sync(0xffffffffu, s, o);
    if (lane == 0) red[warp] = s;
    __syncthreads();
    if (tid == 0) {
        float t = 0.f;
#pragma unroll
        for (int w = 0; w < 8; w++) t += red[w];
        s_mean = t * (1.0f / D_);
    }
    __syncthreads();
    float m = s_mean;

    float v2 = 0.f;
    for (int i = tid; i < D_; i += 256) { float dv = xs[i] - m; v2 += dv * dv; }
#pragma unroll
    for (int o = 16; o; o >>= 1) v2 += __shfl_xor_sync(0xffffffffu, v2, o);
    if (lane == 0) red[warp] = v2;
    __syncthreads();
    if (tid == 0) {
        float t = 0.f;
#pragma unroll
        for (int w = 0; w < 8; w++) t += red[w];
        s_rstd = rsqrtf(t * (1.0f / D_) + 1e-5f);
    }
    __syncthreads();
    float rstd = s_rstd;

    size_t base = (size_t)row * D_;
    for (int i = tid; i < D_; i += 256) {
        float v = (xs[i] - m) * rstd * g[i] + b[i];
        out[base + i] = v;
        bf16 hh, ll; splitv(v, hh, ll);
        oh[base + i] = hh; ol[base + i] = ll;
    }
}

// ---------------- fused QK^T + softmax (fp32, scores stay in smem) ----------------
#define SCP 260
#define QKS_SMEM ((64 * 68 * 2 + 64 * SCP) * 4)

__global__ __launch_bounds__(256)
void qk_softmax_kernel(const float* __restrict__ QKV, float* __restrict__ P)
{
    extern __shared__ float sm[];
    float* Qs = sm;                 // [d][r] pitch 68
    float* Ks = Qs + 64 * 68;       // [d][t] pitch 68
    float* sc = Ks + 64 * 68;       // [r][t] pitch SCP

    const int bh = blockIdx.y;
    const int b = bh / H_, h = bh % H_;
    const int s0 = blockIdx.x * 64;
    const int tid = threadIdx.x;
    const int tx = tid & 15, ty = tid >> 4;

    const float* Qb = QKV + (size_t)b * S_ * QS_ + h * DH_;
    const float* Kb = Qb + 768;

#pragma unroll
    for (int k = 0; k < 16; k++) {
        int idx = tid + k * 256;
        int r = idx >> 6, d = idx & 63;
        float qv = 0.f;
        if (s0 + r < S_) qv = Qb[(size_t)(s0 + r) * QS_ + d];
        Qs[d * 68 + r] = qv;
    }

    for (int tt = 0; tt < 4; tt++) {
        __syncthreads();
#pragma unroll
        for (int k = 0; k < 16; k++) {
            int idx = tid + k * 256;
            int r = idx >> 6, d = idx & 63;
            float kv = 0.f;
            int t = tt * 64 + r;
            if (t < S_) kv = Kb[(size_t)t * QS_ + d];
            Ks[d * 68 + r] = kv;
        }
        __syncthreads();

        float acc[4][4];
#pragma unroll
        for (int i = 0; i < 4; i++)
#pragma unroll
            for (int j = 0; j < 4; j++) acc[i][j] = 0.f;

#pragma unroll 4
        for (int d = 0; d < 64; d++) {
            float4 a  = *reinterpret_cast<const float4*>(&Qs[d * 68 + ty * 4]);
            float4 bb = *reinterpret_cast<const float4*>(&Ks[d * 68 + tx * 4]);
            float ar[4] = {a.x, a.y, a.z, a.w};
            float br[4] = {bb.x, bb.y, bb.z, bb.w};
#pragma unroll
            for (int i = 0; i < 4; i++)
#pragma unroll
                for (int j = 0; j < 4; j++) acc[i][j] += ar[i] * br[j];
        }

#pragma unroll
        for (int i = 0; i < 4; i++)
#pragma unroll
            for (int j = 0; j < 4; j++)
                sc[(ty * 4 + i) * SCP + tt * 64 + tx * 4 + j] = acc[i][j] * 0.125f;
    }
    __syncthreads();

    const int wid = tid >> 5, lane = tid & 31;
    float* Pb = P + (size_t)bh * S_ * S_;
    for (int r = wid * 8; r < wid * 8 + 8; r++) {
        int s = s0 + r;
        if (s >= S_) continue;
        float* row = sc + r * SCP;
        float m = -1e30f;
        for (int t = lane; t < S_; t += 32) m = fmaxf(m, row[t]);
#pragma unroll
        for (int o = 16; o; o >>= 1) m = fmaxf(m, __shfl_xor_sync(0xffffffffu, m, o));
        float ssum = 0.f;
        for (int t = lane; t < S_; t += 32) { float e = expf(row[t] - m); row[t] = e; ssum += e; }
#pragma unroll
        for (int o = 16; o; o >>= 1) ssum += __shfl_xor_sync(0xffffffffu, ssum, o);
        float inv = 1.0f / ssum;
        float* orow = Pb + (size_t)s * S_;
        for (int t = lane; t < S_; t += 32) orow[t] = row[t] * inv;
    }
}

// ---------------- attention: O = P @ V (fp32, writes bf16 hi/lo) ----------------
__global__ __launch_bounds__(256)
void pv_kernel(const float* __restrict__ P, const float* __restrict__ QKV,
               bf16* __restrict__ Oh, bf16* __restrict__ Ol)
{
    const int PITCH = 68;
    __shared__ __align__(16) float Ps[32 * PITCH];
    __shared__ __align__(16) float Vs[32 * PITCH];

    int bh = blockIdx.y;
    int b = bh / H_, h = bh % H_;
    int s0 = blockIdx.x * 64;
    const float* Pb = P + (size_t)bh * S_ * S_;
    const float* Vb = QKV + (size_t)b * S_ * QS_ + 1536 + h * DH_;
    int tid = threadIdx.x;
    int tx = tid & 15, ty = tid >> 4;

    float acc[4][4];
#pragma unroll
    for (int i = 0; i < 4; i++)
#pragma unroll
        for (int j = 0; j < 4; j++) acc[i][j] = 0.f;

    for (int t0 = 0; t0 < S_; t0 += 32) {
#pragma unroll
        for (int k = 0; k < 8; k++) {
            int idx = tid + k * 256;
            int r = idx >> 5, t = idx & 31;
            float pv = 0.f;
            if (s0 + r < S_ && t0 + t < S_) pv = Pb[(size_t)(s0 + r) * S_ + t0 + t];
            Ps[t * PITCH + r] = pv;
        }
#pragma unroll
        for (int k = 0; k < 8; k++) {
            int idx = tid + k * 256;
            int t = idx >> 6, d = idx & 63;
            float vv = 0.f;
            if (t0 + t < S_) vv = Vb[(size_t)(t0 + t) * QS_ + d];
            Vs[t * PITCH + d] = vv;
        }
        __syncthreads();

#pragma unroll 4
        for (int t = 0; t < 32; t++) {
            float4 a = *reinterpret_cast<const float4*>(&Ps[t * PITCH + ty * 4]);
            float4 bb = *reinterpret_cast<const float4*>(&Vs[t * PITCH + tx * 4]);
            float ar[4] = {a.x, a.y, a.z, a.w};
            float br[4] = {bb.x, bb.y, bb.z, bb.w};
#pragma unroll
            for (int i = 0; i < 4; i++)
#pragma unroll
                for (int j = 0; j < 4; j++) acc[i][j] += ar[i] * br[j];
        }
        __syncthreads();
    }

#pragma unroll
    for (int i = 0; i < 4; i++) {
        int s = s0 + ty * 4 + i;
        if (s >= S_) continue;
#pragma unroll
        for (int j = 0; j < 4; j++) {
            int d = tx * 4 + j;
            size_t off = ((size_t)(b * S_ + s)) * D_ + h * DH_ + d;
            bf16 hh, ll; splitv(acc[i][j], hh, ll);
            Oh[off] = hh; Ol[off] = ll;
        }
    }
}

// ---------------- classification head ----------------
__global__ void head_kernel(const float* __restrict__ Xn, const float* __restrict__ W,
                            const float* __restrict__ bias, float* __restrict__ out)
{
    __shared__ float xs[D_];
    int b = blockIdx.y;
    const float* xr = Xn + (size_t)b * S_ * D_;
    for (int i = threadIdx.x; i < D_; i += 256) xs[i] = xr[i];
    __syncthreads();

    int n = blockIdx.x * 256 + threadIdx.x;
    if (n >= NCLS_) return;
    float s = bias[n];
    for (int k = 0; k < D_; k++) s += xs[k] * W[(size_t)k * NCLS_ + n];
    out[b * NCLS_ + n] = s;
}

// ---------------- host launch ----------------
static inline void run_gemm(const bf16* Ah, const bf16* Al, const bf16* Bh, const bf16* Bl,
                            const float* bias, const float* R,
                            float* Cf, bf16* Ch, bf16* Cl, int M, int N, int K, int epi)
{
    dim3 grid(N / 128, (M + 127) / 128);
    gemm_dual_kernel<<<grid, 256, GEMM_SMEM>>>(Ah, Al, Bh, Bl, bias, R, Cf, Ch, Cl, M, N, K, epi);
}

extern "C" void kernel_launch(void* const* d_in, const int* in_sizes, int n_in,
                              void* d_out, int out_size)
{
    const float* X       = (const float*)d_in[0];
    const float* patch_w = (const float*)d_in[1];
    const float* patch_b = (const float*)d_in[2];
    const float* cls_tok = (const float*)d_in[3];
    const float* pos_emb = (const float*)d_in[4];
    const float* ln1_g   = (const float*)d_in[5];
    const float* ln1_b   = (const float*)d_in[6];
    const float* Wq      = (const float*)d_in[7];
    const float* bq      = (const float*)d_in[8];
    const float* Wk      = (const float*)d_in[9];
    const float* bk      = (const float*)d_in[10];
    const float* Wv      = (const float*)d_in[11];
    const float* bv      = (const float*)d_in[12];
    const float* Wo      = (const float*)d_in[13];
    const float* bo      = (const float*)d_in[14];
    const float* ln2_g   = (const float*)d_in[15];
    const float* ln2_b   = (const float*)d_in[16];
    const float* Wf1     = (const float*)d_in[17];
    const float* bf1     = (const float*)d_in[18];
    const float* Wf2     = (const float*)d_in[19];
    const float* bf2     = (const float*)d_in[20];
    const float* lnf_g   = (const float*)d_in[21];
    const float* lnf_b   = (const float*)d_in[22];
    const float* head_w  = (const float*)d_in[23];
    const float* head_b  = (const float*)d_in[24];
    float* out = (float*)d_out;
    (void)in_sizes; (void)n_in; (void)out_size;

    cudaFuncSetAttribute(gemm_dual_kernel, cudaFuncAttributeMaxDynamicSharedMemorySize, GEMM_SMEM);
    cudaFuncSetAttribute(qk_softmax_kernel, cudaFuncAttributeMaxDynamicSharedMemorySize, QKS_SMEM);

    float *px, *plnf, *pqkv, *ppe, *psc, *pbqkv;
    bf16 *plnh, *plnl, *pattnh, *pattnl, *pffhh, *pffhl, *pimh, *piml;
    bf16 *pwpth, *pwptl, *pwqkvh, *pwqkvl, *pwoh, *pwol, *pwf1h, *pwf1l, *pwf2h, *pwf2l;
    cudaGetSymbolAddress((void**)&px,    g_x);
    cudaGetSymbolAddress((void**)&plnf,  g_lnb);
    cudaGetSymbolAddress((void**)&plnh,  g_lnh);
    cudaGetSymbolAddress((void**)&plnl,  g_lnl);
    cudaGetSymbolAddress((void**)&pqkv,  g_qkv);
    cudaGetSymbolAddress((void**)&pattnh,g_attnh);
    cudaGetSymbolAddress((void**)&pattnl,g_attnl);
    cudaGetSymbolAddress((void**)&pffhh, g_ffhh);
    cudaGetSymbolAddress((void**)&pffhl, g_ffhl);
    cudaGetSymbolAddress((void**)&psc,   g_sc);
    cudaGetSymbolAddress((void**)&pimh,  g_imh);
    cudaGetSymbolAddress((void**)&piml,  g_iml);
    cudaGetSymbolAddress((void**)&ppe,   g_pe);
    cudaGetSymbolAddress((void**)&pwpth, g_wpt_h);
    cudaGetSymbolAddress((void**)&pwptl, g_wpt_l);
    cudaGetSymbolAddress((void**)&pwqkvh,g_wqkv_h);
    cudaGetSymbolAddress((void**)&pwqkvl,g_wqkv_l);
    cudaGetSymbolAddress((void**)&pbqkv, g_bqkv);
    cudaGetSymbolAddress((void**)&pwoh,  g_wo_h);
    cudaGetSymbolAddress((void**)&pwol,  g_wo_l);
    cudaGetSymbolAddress((void**)&pwf1h, g_wf1_h);
    cudaGetSymbolAddress((void**)&pwf1l, g_wf1_l);
    cudaGetSymbolAddress((void**)&pwf2h, g_wf2_h);
    cudaGetSymbolAddress((void**)&pwf2l, g_wf2_l);

    // --- prep: split weights (vectorized) ---
    {
        size_t nqkv = (size_t)L_ * D_ * QS_;
        qkv_split_kernel<<<(unsigned)((nqkv / 4 + 255) / 256), 256>>>(Wq, Wk, Wv, pwqkvh, pwqkvl);
        qkv_bias_kernel<<<(L_ * QS_ + 255) / 256, 256>>>(bq, bk, bv, pbqkv);
        size_t nwo = (size_t)L_ * D_ * D_;
        split_kernel<<<(unsigned)((nwo / 4 + 255) / 256), 256>>>(Wo, pwoh, pwol, nwo);
        size_t nf = (size_t)L_ * D_ * F_;
        split_kernel<<<(unsigned)((nf / 4 + 255) / 256), 256>>>(Wf1, pwf1h, pwf1l, nf);
        split_kernel<<<(unsigned)((nf / 4 + 255) / 256), 256>>>(Wf2, pwf2h, pwf2l, nf);
        transpose_split_kernel<<<(D_ * D_ + 255) / 256, 256>>>(patch_w, pwpth, pwptl);
    }

    // --- patch embedding ---
    {
        int n1 = B_ * NPATCH * D_;
        im2col_kernel<<<(n1 + 255) / 256, 256>>>(X, pimh, piml);
        run_gemm(pimh, piml, pwpth, pwptl, patch_b, nullptr,
                 ppe, nullptr, nullptr, B_ * NPATCH, D_, D_, 0);
        int n2 = BS_ * D_;
        assemble_kernel<<<(n2 + 255) / 256, 256>>>(ppe, cls_tok, pos_emb, px);
    }

    for (int l = 0; l < L_; l++) {
        layernorm_kernel<<<BS_, 256>>>(px, ln1_g + l * D_, ln1_b + l * D_, plnf, plnh, plnl);

        // fused QKV GEMM -> fp32 qkv
        run_gemm(plnh, plnl, pwqkvh + (size_t)l * D_ * QS_, pwqkvl + (size_t)l * D_ * QS_,
                 pbqkv + l * QS_, nullptr, pqkv, nullptr, nullptr, BS_, QS_, D_, 0);

        // fused QK^T + softmax, then PV
        {
            dim3 grid((S_ + 63) / 64, B_ * H_);
            qk_softmax_kernel<<<grid, 256, QKS_SMEM>>>(pqkv, psc);
            pv_kernel<<<grid, 256>>>(psc, pqkv, pattnh, pattnl);
        }

        // out proj + residual
        run_gemm(pattnh, pattnl, pwoh + (size_t)l * D_ * D_, pwol + (size_t)l * D_ * D_,
                 bo + l * D_, px, px, nullptr, nullptr, BS_, D_, D_, 1);

        layernorm_kernel<<<BS_, 256>>>(px, ln2_g + l * D_, ln2_b + l * D_, plnf, plnh, plnl);

        // FFN1 (GELU) + FFN2 (+residual)
        run_gemm(plnh, plnl, pwf1h + (size_t)l * D_ * F_, pwf1l + (size_t)l * D_ * F_,
                 bf1 + l * F_, nullptr, nullptr, pffhh, pffhl, BS_, F_, D_, 2);
        run_gemm(pffhh, pffhl, pwf2h + (size_t)l * F_ * D_, pwf2l + (size_t)l * F_ * D_,
                 bf2 + l * D_, px, px, nullptr, nullptr, BS_, D_, F_, 1);
    }

    layernorm_kernel<<<BS_, 256>>>(px, lnf_g, lnf_b, plnf, plnh, plnl);
    {
        dim3 grid((NCLS_ + 255) / 256, B_);
        head_kernel<<<grid, 256>>>(plnf, head_w, head_b, out);
    }
}

// round 16
// speedup vs baseline: 1.5030x; 1.4755x over previous
#include <cuda_runtime.h>
#include <cuda_fp16.h>
#include <mma.h>
#include <math.h>
#include <stdint.h>

using namespace nvcuda;

// ---------------- problem constants ----------------
#define B_     32
#define S_     197
#define BS_    (B_ * S_)      // 6304
#define D_     768
#define F_     3072
#define H_     12
#define DH_    64
#define L_     12
#define NPATCH 196
#define NCLS_  1000
#define QS_    2304           // fused qkv row stride

typedef __half fp16;

// ---------------- scratch ----------------
__device__ float g_x   [BS_ * D_];
__device__ float g_lnb [BS_ * D_];
__device__ fp16  g_ln  [BS_ * D_];
__device__ float g_qkv [(size_t)BS_ * QS_];
__device__ fp16  g_attn[BS_ * D_];
__device__ fp16  g_ffh [(size_t)BS_ * F_];
__device__ float g_sc  [(size_t)B_ * H_ * S_ * S_];
__device__ fp16  g_im  [B_ * NPATCH * D_];
__device__ float g_pe  [B_ * NPATCH * D_];
// pre-split weights (fp16 hi/lo), [K,N] layout
__device__ fp16  g_wpt_h[D_ * D_];
__device__ fp16  g_wpt_l[D_ * D_];
__device__ fp16  g_wqkv_h[(size_t)L_ * D_ * QS_];
__device__ fp16  g_wqkv_l[(size_t)L_ * D_ * QS_];
__device__ float g_bqkv [L_ * QS_];
__device__ fp16  g_wo_h[(size_t)L_ * D_ * D_];
__device__ fp16  g_wo_l[(size_t)L_ * D_ * D_];
__device__ fp16  g_wf1_h[(size_t)L_ * D_ * F_];
__device__ fp16  g_wf1_l[(size_t)L_ * D_ * F_];
__device__ fp16  g_wf2_h[(size_t)L_ * F_ * D_];
__device__ fp16  g_wf2_l[(size_t)L_ * F_ * D_];

// ---------------- helpers ----------------
__device__ __forceinline__ void splitv(float v, fp16& h, fp16& l) {
    h = __float2half(v);
    l = __float2half(v - __half2float(h));
}
__device__ __forceinline__ uint32_t smem_u32(const void* p) {
    return (uint32_t)__cvta_generic_to_shared(p);
}
__device__ __forceinline__ void cp16(uint32_t dst, const void* src, bool pred) {
    int sz = pred ? 16 : 0;
    asm volatile("cp.async.cg.shared.global [%0], [%1], 16, %2;\n"
                 :: "r"(dst), "l"(src), "r"(sz));
}

// ---------------- prep: weight splitting (vectorized x4) ----------------
__global__ void split_kernel(const float* __restrict__ src, fp16* __restrict__ h,
                             fp16* __restrict__ l, size_t n) {
    size_t i = ((size_t)blockIdx.x * 256 + threadIdx.x) * 4;
    if (i >= n) return;
    float4 v = *reinterpret_cast<const float4*>(src + i);
    fp16 h0,l0,h1,l1,h2,l2,h3,l3;
    splitv(v.x,h0,l0); splitv(v.y,h1,l1); splitv(v.z,h2,l2); splitv(v.w,h3,l3);
    *reinterpret_cast<__half2*>(h + i)     = __halves2half2(h0, h1);
    *reinterpret_cast<__half2*>(h + i + 2) = __halves2half2(h2, h3);
    *reinterpret_cast<__half2*>(l + i)     = __halves2half2(l0, l1);
    *reinterpret_cast<__half2*>(l + i + 2) = __halves2half2(l2, l3);
}

__global__ void qkv_split_kernel(const float* __restrict__ Wq, const float* __restrict__ Wk,
                                 const float* __restrict__ Wv,
                                 fp16* __restrict__ h, fp16* __restrict__ l) {
    size_t i = ((size_t)blockIdx.x * 256 + threadIdx.x) * 4;
    if (i >= (size_t)L_ * D_ * QS_) return;
    int n = (int)(i % QS_);
    size_t rest = i / QS_;
    int k = (int)(rest % D_);
    int lay = (int)(rest / D_);
    const float* src = (n < 768) ? Wq : (n < 1536) ? Wk : Wv;
    float4 v = *reinterpret_cast<const float4*>(src + ((size_t)lay * D_ + k) * D_ + (n % 768));
    fp16 h0,l0,h1,l1,h2,l2,h3,l3;
    splitv(v.x,h0,l0); splitv(v.y,h1,l1); splitv(v.z,h2,l2); splitv(v.w,h3,l3);
    *reinterpret_cast<__half2*>(h + i)     = __halves2half2(h0, h1);
    *reinterpret_cast<__half2*>(h + i + 2) = __halves2half2(h2, h3);
    *reinterpret_cast<__half2*>(l + i)     = __halves2half2(l0, l1);
    *reinterpret_cast<__half2*>(l + i + 2) = __halves2half2(l2, l3);
}

__global__ void qkv_bias_kernel(const float* __restrict__ bq, const float* __restrict__ bk,
                                const float* __restrict__ bv, float* __restrict__ out) {
    int i = blockIdx.x * 256 + threadIdx.x;
    if (i >= L_ * QS_) return;
    int n = i % QS_, lay = i / QS_;
    const float* src = (n < 768) ? bq : (n < 1536) ? bk : bv;
    out[i] = src[lay * D_ + (n % 768)];
}

__global__ void transpose_split_kernel(const float* __restrict__ W,
                                       fp16* __restrict__ h, fp16* __restrict__ l) {
    int idx = blockIdx.x * 256 + threadIdx.x;
    if (idx >= D_ * D_) return;
    int d = idx / D_, k = idx % D_;
    splitv(W[idx], h[k * D_ + d], l[k * D_ + d]);
}

// ---------------- im2col (writes fp16) ----------------
__global__ void im2col_kernel(const float* __restrict__ X, fp16* __restrict__ o) {
    int idx = blockIdx.x * blockDim.x + threadIdx.x;
    if (idx >= B_ * NPATCH * D_) return;
    int col = idx % D_;
    int row = idx / D_;
    int b  = row / NPATCH;
    int pp = row % NPATCH;
    int ph = pp / 14, pw = pp % 14;
    int c = col >> 8;
    int p = (col >> 4) & 15;
    int q = col & 15;
    o[idx] = __float2half(X[((size_t)(b * 3 + c) * 224 + (ph * 16 + p)) * 224 + (pw * 16 + q)]);
}

__global__ void assemble_kernel(const float* __restrict__ pe, const float* __restrict__ cls,
                                const float* __restrict__ pos, float* __restrict__ x) {
    int idx = blockIdx.x * blockDim.x + threadIdx.x;
    if (idx >= BS_ * D_) return;
    int d  = idx % D_;
    int bs = idx / D_;
    int s = bs % S_;
    int b = bs / S_;
    float v = (s == 0) ? cls[d] : pe[((size_t)b * NPATCH + (s - 1)) * D_ + d];
    x[idx] = v + pos[s * D_ + d];
}

// ---------------- fp16 2-term tensor-core GEMM ----------------
// C = A(fp16) @ (Bh + Bl)(fp16 hi/lo), fp32 accumulate. 2 MMAs per tile pair.
// BM=128 BN=256 BK=32, 512 threads (16 warps, 4x4, warp tile 32x64).
// epi: 0 -> Cf = v ; 1 -> Cf = v + R ; 2 -> Ch = fp16(GELU(v))
#define PA 40
#define PB 264
#define GEMM_SMEM 108544

__global__ __launch_bounds__(512, 1)
void gemm_dual_kernel(const fp16* __restrict__ Ag,
                      const fp16* __restrict__ Bgh, const fp16* __restrict__ Bgl,
                      const float* __restrict__ bias, const float* __restrict__ R,
                      float* __restrict__ Cf, fp16* __restrict__ Ch,
                      int M, int N, int K, int epi)
{
    extern __shared__ char dsm[];
    fp16* sA  = (fp16*)dsm;                       // 2 * 128*PA
    fp16* sBh = sA + 2 * 128 * PA;                // 2 * 32*PB
    fp16* sBl = sBh + 2 * 32 * PB;
    float* sStage = (float*)(sBl + 2 * 32 * PB);  // 16 * 16*20

    const int tid  = threadIdx.x;
    const int wid  = tid >> 5;
    const int lane = tid & 31;
    const int warpRow = wid >> 2;     // 0..3 (32 rows)
    const int warpCol = wid & 3;      // 0..3 (64 cols)
    const int brow = blockIdx.y * 128;
    const int bcol = blockIdx.x * 256;

    // A loader: 512 chunks (128 rows x 4), 1 per thread
    const int arow = tid >> 2;
    const int ac8  = (tid & 3) * 8;
    const bool aOk = (brow + arow) < M;
    const int aRowG = aOk ? (brow + arow) : (M - 1);
    const fp16* aSrc = Ag + (size_t)aRowG * K + ac8;
    const uint32_t aDst = smem_u32(sA + arow * PA + ac8);
    // B loader: 1024 chunks (32 rows x 32), 2 per thread (for hi and lo each)
    const int brow0 = tid >> 5,          bcc0 = (tid & 31) * 8;
    const int brow1 = (tid + 512) >> 5,  bcc1 = bcc0;
    const uint32_t bDstH0 = smem_u32(sBh + brow0 * PB + bcc0);
    const uint32_t bDstH1 = smem_u32(sBh + brow1 * PB + bcc1);
    const uint32_t bDstL0 = smem_u32(sBl + brow0 * PB + bcc0);
    const uint32_t bDstL1 = smem_u32(sBl + brow1 * PB + bcc1);

    const int bufA = 128 * PA * 2;
    const int bufB = 32 * PB * 2;

    auto issue = [&](int k0, int buf) {
        cp16(aDst + buf * bufA, aSrc + k0, aOk);
        const fp16* bh = Bgh + (size_t)k0 * N + bcol;
        const fp16* bl = Bgl + (size_t)k0 * N + bcol;
        cp16(bDstH0 + buf * bufB, bh + (size_t)brow0 * N + bcc0, true);
        cp16(bDstH1 + buf * bufB, bh + (size_t)brow1 * N + bcc1, true);
        cp16(bDstL0 + buf * bufB, bl + (size_t)brow0 * N + bcc0, true);
        cp16(bDstL1 + buf * bufB, bl + (size_t)brow1 * N + bcc1, true);
    };

    wmma::fragment<wmma::accumulator, 16, 16, 16, float> acc[2][4];
#pragma unroll
    for (int i = 0; i < 2; i++)
#pragma unroll
        for (int j = 0; j < 4; j++) wmma::fill_fragment(acc[i][j], 0.0f);

    const int T = K / 32;
    issue(0, 0);
    asm volatile("cp.async.commit_group;\n");
    asm volatile("cp.async.wait_group 0;\n");
    __syncthreads();

    for (int it = 0; it < T; ++it) {
        if (it + 1 < T) {
            issue((it + 1) * 32, (it + 1) & 1);
            asm volatile("cp.async.commit_group;\n");
        }

        const int buf = it & 1;
        const fp16* cA  = sA + buf * 128 * PA;
        const fp16* cBh = sBh + buf * 32 * PB;
        const fp16* cBl = sBl + buf * 32 * PB;

#pragma unroll
        for (int kk = 0; kk < 32; kk += 16) {
            wmma::fragment<wmma::matrix_b, 16, 16, 16, fp16, wmma::row_major> fbh[4], fbl[4];
#pragma unroll
            for (int j = 0; j < 4; j++) {
                wmma::load_matrix_sync(fbh[j], cBh + kk * PB + warpCol * 64 + j * 16, PB);
                wmma::load_matrix_sync(fbl[j], cBl + kk * PB + warpCol * 64 + j * 16, PB);
            }
#pragma unroll
            for (int i = 0; i < 2; i++) {
                wmma::fragment<wmma::matrix_a, 16, 16, 16, fp16, wmma::row_major> fa;
                int r = warpRow * 32 + i * 16;
                wmma::load_matrix_sync(fa, cA + r * PA + kk, PA);
#pragma unroll
                for (int j = 0; j < 4; j++) {
                    wmma::mma_sync(acc[i][j], fa, fbh[j], acc[i][j]);
                    wmma::mma_sync(acc[i][j], fa, fbl[j], acc[i][j]);
                }
            }
        }

        if (it + 1 < T) asm volatile("cp.async.wait_group 0;\n");
        __syncthreads();
    }

    // ---- epilogue ----
    float* st = sStage + wid * 16 * 20;
#pragma unroll
    for (int i = 0; i < 2; i++) {
#pragma unroll
        for (int j = 0; j < 4; j++) {
            wmma::store_matrix_sync(st, acc[i][j], 20, wmma::mem_row_major);
            __syncwarp();
            int gr0 = brow + warpRow * 32 + i * 16;
            int gc0 = bcol + warpCol * 64 + j * 16;
#pragma unroll
            for (int e = 0; e < 8; e++) {
                int idx = e * 32 + lane;
                int r = idx >> 4, c = idx & 15;
                int gr = gr0 + r;
                if (gr < M) {
                    size_t off = (size_t)gr * N + gc0 + c;
                    float v = st[r * 20 + c] + bias[gc0 + c];
                    if (epi == 1) {
                        Cf[off] = v + R[off];
                    } else if (epi == 2) {
                        v = 0.5f * v * (1.0f + erff(v * 0.70710678118654752f));
                        Ch[off] = __float2half(v);
                    } else {
                        Cf[off] = v;
                    }
                }
            }
            __syncwarp();
        }
    }
}

// ---------------- LayerNorm (fp32 out + fp16 out) ----------------
__global__ void layernorm_kernel(const float* __restrict__ x, const float* __restrict__ g,
                                 const float* __restrict__ b, float* __restrict__ out,
                                 fp16* __restrict__ oh)
{
    __shared__ float xs[D_];
    __shared__ float red[8];
    __shared__ float s_mean, s_rstd;

    int row = blockIdx.x;
    const float* xr = x + (size_t)row * D_;
    int tid  = threadIdx.x;
    int lane = tid & 31, warp = tid >> 5;

    float s = 0.f;
    for (int i = tid; i < D_; i += 256) { float v = xr[i]; xs[i] = v; s += v; }
#pragma unroll
    for (int o = 16; o; o >>= 1) s += __shfl_xor_sync(0xffffffffu, s, o);
    if (lane == 0) red[warp] = s;
    __syncthreads();
    if (tid == 0) {
        float t = 0.f;
#pragma unroll
        for (int w = 0; w < 8; w++) t += red[w];
        s_mean = t * (1.0f / D_);
    }
    __syncthreads();
    float m = s_mean;

    float v2 = 0.f;
    for (int i = tid; i < D_; i += 256) { float dv = xs[i] - m; v2 += dv * dv; }
#pragma unroll
    for (int o = 16; o; o >>= 1) v2 += __shfl_xor_sync(0xffffffffu, v2, o);
    if (lane == 0) red[warp] = v2;
    __syncthreads();
    if (tid == 0) {
        float t = 0.f;
#pragma unroll
        for (int w = 0; w < 8; w++) t += red[w];
        s_rstd = rsqrtf(t * (1.0f / D_) + 1e-5f);
    }
    __syncthreads();
    float rstd = s_rstd;

    size_t base = (size_t)row * D_;
    for (int i = tid; i < D_; i += 256) {
        float v = (xs[i] - m) * rstd * g[i] + b[i];
        out[base + i] = v;
        oh[base + i] = __float2half(v);
    }
}

// ---------------- fused QK^T + softmax (fp32, scores stay in smem) ----------------
#define SCP 260
#define QKS_SMEM ((64 * 68 * 2 + 64 * SCP) * 4)

__global__ __launch_bounds__(256)
void qk_softmax_kernel(const float* __restrict__ QKV, float* __restrict__ P)
{
    extern __shared__ float sm[];
    float* Qs = sm;                 // [d][r] pitch 68
    float* Ks = Qs + 64 * 68;       // [d][t] pitch 68
    float* sc = Ks + 64 * 68;       // [r][t] pitch SCP

    const int bh = blockIdx.y;
    const int b = bh / H_, h = bh % H_;
    const int s0 = blockIdx.x * 64;
    const int tid = threadIdx.x;
    const int tx = tid & 15, ty = tid >> 4;

    const float* Qb = QKV + (size_t)b * S_ * QS_ + h * DH_;
    const float* Kb = Qb + 768;

#pragma unroll
    for (int k = 0; k < 16; k++) {
        int idx = tid + k * 256;
        int r = idx >> 6, d = idx & 63;
        float qv = 0.f;
        if (s0 + r < S_) qv = Qb[(size_t)(s0 + r) * QS_ + d];
        Qs[d * 68 + r] = qv;
    }

    for (int tt = 0; tt < 4; tt++) {
        __syncthreads();
#pragma unroll
        for (int k = 0; k < 16; k++) {
            int idx = tid + k * 256;
            int r = idx >> 6, d = idx & 63;
            float kv = 0.f;
            int t = tt * 64 + r;
            if (t < S_) kv = Kb[(size_t)t * QS_ + d];
            Ks[d * 68 + r] = kv;
        }
        __syncthreads();

        float acc[4][4];
#pragma unroll
        for (int i = 0; i < 4; i++)
#pragma unroll
            for (int j = 0; j < 4; j++) acc[i][j] = 0.f;

#pragma unroll 4
        for (int d = 0; d < 64; d++) {
            float4 a  = *reinterpret_cast<const float4*>(&Qs[d * 68 + ty * 4]);
            float4 bb = *reinterpret_cast<const float4*>(&Ks[d * 68 + tx * 4]);
            float ar[4] = {a.x, a.y, a.z, a.w};
            float br[4] = {bb.x, bb.y, bb.z, bb.w};
#pragma unroll
            for (int i = 0; i < 4; i++)
#pragma unroll
                for (int j = 0; j < 4; j++) acc[i][j] += ar[i] * br[j];
        }

#pragma unroll
        for (int i = 0; i < 4; i++)
#pragma unroll
            for (int j = 0; j < 4; j++)
                sc[(ty * 4 + i) * SCP + tt * 64 + tx * 4 + j] = acc[i][j] * 0.125f;
    }
    __syncthreads();

    const int wid = tid >> 5, lane = tid & 31;
    float* Pb = P + (size_t)bh * S_ * S_;
    for (int r = wid * 8; r < wid * 8 + 8; r++) {
        int s = s0 + r;
        if (s >= S_) continue;
        float* row = sc + r * SCP;
        float m = -1e30f;
        for (int t = lane; t < S_; t += 32) m = fmaxf(m, row[t]);
#pragma unroll
        for (int o = 16; o; o >>= 1) m = fmaxf(m, __shfl_xor_sync(0xffffffffu, m, o));
        float ssum = 0.f;
        for (int t = lane; t < S_; t += 32) { float e = expf(row[t] - m); row[t] = e; ssum += e; }
#pragma unroll
        for (int o = 16; o; o >>= 1) ssum += __shfl_xor_sync(0xffffffffu, ssum, o);
        float inv = 1.0f / ssum;
        float* orow = Pb + (size_t)s * S_;
        for (int t = lane; t < S_; t += 32) orow[t] = row[t] * inv;
    }
}

// ---------------- attention: O = P @ V (fp32, writes fp16) ----------------
__global__ __launch_bounds__(256)
void pv_kernel(const float* __restrict__ P, const float* __restrict__ QKV,
               fp16* __restrict__ O)
{
    const int PITCH = 68;
    __shared__ __align__(16) float Ps[32 * PITCH];
    __shared__ __align__(16) float Vs[32 * PITCH];

    int bh = blockIdx.y;
    int b = bh / H_, h = bh % H_;
    int s0 = blockIdx.x * 64;
    const float* Pb = P + (size_t)bh * S_ * S_;
    const float* Vb = QKV + (size_t)b * S_ * QS_ + 1536 + h * DH_;
    int tid = threadIdx.x;
    int tx = tid & 15, ty = tid >> 4;

    float acc[4][4];
#pragma unroll
    for (int i = 0; i < 4; i++)
#pragma unroll
        for (int j = 0; j < 4; j++) acc[i][j] = 0.f;

    for (int t0 = 0; t0 < S_; t0 += 32) {
#pragma unroll
        for (int k = 0; k < 8; k++) {
            int idx = tid + k * 256;
            int r = idx >> 5, t = idx & 31;
            float pv = 0.f;
            if (s0 + r < S_ && t0 + t < S_) pv = Pb[(size_t)(s0 + r) * S_ + t0 + t];
            Ps[t * PITCH + r] = pv;
        }
#pragma unroll
        for (int k = 0; k < 8; k++) {
            int idx = tid + k * 256;
            int t = idx >> 6, d = idx & 63;
            float vv = 0.f;
            if (t0 + t < S_) vv = Vb[(size_t)(t0 + t) * QS_ + d];
            Vs[t * PITCH + d] = vv;
        }
        __syncthreads();

#pragma unroll 4
        for (int t = 0; t < 32; t++) {
            float4 a = *reinterpret_cast<const float4*>(&Ps[t * PITCH + ty * 4]);
            float4 bb = *reinterpret_cast<const float4*>(&Vs[t * PITCH + tx * 4]);
            float ar[4] = {a.x, a.y, a.z, a.w};
            float br[4] = {bb.x, bb.y, bb.z, bb.w};
#pragma unroll
            for (int i = 0; i < 4; i++)
#pragma unroll
                for (int j = 0; j < 4; j++) acc[i][j] += ar[i] * br[j];
        }
        __syncthreads();
    }

#pragma unroll
    for (int i = 0; i < 4; i++) {
        int s = s0 + ty * 4 + i;
        if (s >= S_) continue;
#pragma unroll
        for (int j = 0; j < 4; j++) {
            int d = tx * 4 + j;
            size_t off = ((size_t)(b * S_ + s)) * D_ + h * DH_ + d;
            O[off] = __float2half(acc[i][j]);
        }
    }
}

// ---------------- classification head ----------------
__global__ void head_kernel(const float* __restrict__ Xn, const float* __restrict__ W,
                            const float* __restrict__ bias, float* __restrict__ out)
{
    __shared__ float xs[D_];
    int b = blockIdx.y;
    const float* xr = Xn + (size_t)b * S_ * D_;
    for (int i = threadIdx.x; i < D_; i += 256) xs[i] = xr[i];
    __syncthreads();

    int n = blockIdx.x * 256 + threadIdx.x;
    if (n >= NCLS_) return;
    float s = bias[n];
    for (int k = 0; k < D_; k++) s += xs[k] * W[(size_t)k * NCLS_ + n];
    out[b * NCLS_ + n] = s;
}

// ---------------- host launch ----------------
static inline void run_gemm(const fp16* A, const fp16* Bh, const fp16* Bl,
                            const float* bias, const float* R,
                            float* Cf, fp16* Ch, int M, int N, int K, int epi)
{
    dim3 grid(N / 256, (M + 127) / 128);
    gemm_dual_kernel<<<grid, 512, GEMM_SMEM>>>(A, Bh, Bl, bias, R, Cf, Ch, M, N, K, epi);
}

extern "C" void kernel_launch(void* const* d_in, const int* in_sizes, int n_in,
                              void* d_out, int out_size)
{
    const float* X       = (const float*)d_in[0];
    const float* patch_w = (const float*)d_in[1];
    const float* patch_b = (const float*)d_in[2];
    const float* cls_tok = (const float*)d_in[3];
    const float* pos_emb = (const float*)d_in[4];
    const float* ln1_g   = (const float*)d_in[5];
    const float* ln1_b   = (const float*)d_in[6];
    const float* Wq      = (const float*)d_in[7];
    const float* bq      = (const float*)d_in[8];
    const float* Wk      = (const float*)d_in[9];
    const float* bk      = (const float*)d_in[10];
    const float* Wv      = (const float*)d_in[11];
    const float* bv      = (const float*)d_in[12];
    const float* Wo      = (const float*)d_in[13];
    const float* bo      = (const float*)d_in[14];
    const float* ln2_g   = (const float*)d_in[15];
    const float* ln2_b   = (const float*)d_in[16];
    const float* Wf1     = (const float*)d_in[17];
    const float* bf1     = (const float*)d_in[18];
    const float* Wf2     = (const float*)d_in[19];
    const float* bf2     = (const float*)d_in[20];
    const float* lnf_g   = (const float*)d_in[21];
    const float* lnf_b   = (const float*)d_in[22];
    const float* head_w  = (const float*)d_in[23];
    const float* head_b  = (const float*)d_in[24];
    float* out = (float*)d_out;
    (void)in_sizes; (void)n_in; (void)out_size;

    cudaFuncSetAttribute(gemm_dual_kernel, cudaFuncAttributeMaxDynamicSharedMemorySize, GEMM_SMEM);
    cudaFuncSetAttribute(qk_softmax_kernel, cudaFuncAttributeMaxDynamicSharedMemorySize, QKS_SMEM);

    float *px, *plnf, *pqkv, *ppe, *psc, *pbqkv;
    fp16 *pln, *pattn, *pffh, *pim;
    fp16 *pwpth, *pwptl, *pwqkvh, *pwqkvl, *pwoh, *pwol, *pwf1h, *pwf1l, *pwf2h, *pwf2l;
    cudaGetSymbolAddress((void**)&px,    g_x);
    cudaGetSymbolAddress((void**)&plnf,  g_lnb);
    cudaGetSymbolAddress((void**)&pln,   g_ln);
    cudaGetSymbolAddress((void**)&pqkv,  g_qkv);
    cudaGetSymbolAddress((void**)&pattn, g_attn);
    cudaGetSymbolAddress((void**)&pffh,  g_ffh);
    cudaGetSymbolAddress((void**)&psc,   g_sc);
    cudaGetSymbolAddress((void**)&pim,   g_im);
    cudaGetSymbolAddress((void**)&ppe,   g_pe);
    cudaGetSymbolAddress((void**)&pwpth, g_wpt_h);
    cudaGetSymbolAddress((void**)&pwptl, g_wpt_l);
    cudaGetSymbolAddress((void**)&pwqkvh,g_wqkv_h);
    cudaGetSymbolAddress((void**)&pwqkvl,g_wqkv_l);
    cudaGetSymbolAddress((void**)&pbqkv, g_bqkv);
    cudaGetSymbolAddress((void**)&pwoh,  g_wo_h);
    cudaGetSymbolAddress((void**)&pwol,  g_wo_l);
    cudaGetSymbolAddress((void**)&pwf1h, g_wf1_h);
    cudaGetSymbolAddress((void**)&pwf1l, g_wf1_l);
    cudaGetSymbolAddress((void**)&pwf2h, g_wf2_h);
    cudaGetSymbolAddress((void**)&pwf2l, g_wf2_l);

    // --- prep: split weights (vectorized) ---
    {
        size_t nqkv = (size_t)L_ * D_ * QS_;
        qkv_split_kernel<<<(unsigned)((nqkv / 4 + 255) / 256), 256>>>(Wq, Wk, Wv, pwqkvh, pwqkvl);
        qkv_bias_kernel<<<(L_ * QS_ + 255) / 256, 256>>>(bq, bk, bv, pbqkv);
        size_t nwo = (size_t)L_ * D_ * D_;
        split_kernel<<<(unsigned)((nwo / 4 + 255) / 256), 256>>>(Wo, pwoh, pwol, nwo);
        size_t nf = (size_t)L_ * D_ * F_;
        split_kernel<<<(unsigned)((nf / 4 + 255) / 256), 256>>>(Wf1, pwf1h, pwf1l, nf);
        split_kernel<<<(unsigned)((nf / 4 + 255) / 256), 256>>>(Wf2, pwf2h, pwf2l, nf);
        transpose_split_kernel<<<(D_ * D_ + 255) / 256, 256>>>(patch_w, pwpth, pwptl);
    }

    // --- patch embedding ---
    {
        int n1 = B_ * NPATCH * D_;
        im2col_kernel<<<(n1 + 255) / 256, 256>>>(X, pim);
        run_gemm(pim, pwpth, pwptl, patch_b, nullptr,
                 ppe, nullptr, B_ * NPATCH, D_, D_, 0);
        int n2 = BS_ * D_;
        assemble_kernel<<<(n2 + 255) / 256, 256>>>(ppe, cls_tok, pos_emb, px);
    }

    for (int l = 0; l < L_; l++) {
        layernorm_kernel<<<BS_, 256>>>(px, ln1_g + l * D_, ln1_b + l * D_, plnf, pln);

        // fused QKV GEMM -> fp32 qkv
        run_gemm(pln, pwqkvh + (size_t)l * D_ * QS_, pwqkvl + (size_t)l * D_ * QS_,
                 pbqkv + l * QS_, nullptr, pqkv, nullptr, BS_, QS_, D_, 0);

        // fused QK^T + softmax, then PV
        {
            dim3 grid((S_ + 63) / 64, B_ * H_);
            qk_softmax_kernel<<<grid, 256, QKS_SMEM>>>(pqkv, psc);
            pv_kernel<<<grid, 256>>>(psc, pqkv, pattn);
        }

        // out proj + residual
        run_gemm(pattn, pwoh + (size_t)l * D_ * D_, pwol + (size_t)l * D_ * D_,
                 bo + l * D_, px, px, nullptr, BS_, D_, D_, 1);

        layernorm_kernel<<<BS_, 256>>>(px, ln2_g + l * D_, ln2_b + l * D_, plnf, pln);

        // FFN1 (GELU) + FFN2 (+residual)
        run_gemm(pln, pwf1h + (size_t)l * D_ * F_, pwf1l + (size_t)l * D_ * F_,
                 bf1 + l * F_, nullptr, nullptr, pffh, BS_, F_, D_, 2);
        run_gemm(pffh, pwf2h + (size_t)l * F_ * D_, pwf2l + (size_t)l * F_ * D_,
                 bf2 + l * D_, px, px, nullptr, BS_, D_, F_, 1);
    }

    layernorm_kernel<<<BS_, 256>>>(px, lnf_g, lnf_b, plnf, pln);
    {
        dim3 grid((NCLS_ + 255) / 256, B_);
        head_kernel<<<grid, 256>>>(plnf, head_w, head_b, out);
    }
}